// round 1
// baseline (speedup 1.0000x reference)
#include <cuda_runtime.h>

// SRNN_Softmax: one stack-RNN step.
//   emb   = E[inp[0]]                       (V,)
//   hbar  = W_sh[:,0]*stack[0] + b_sh + hidden0          (H,)
//   h     = tanh(W_ih@emb + b_ih + W_hh@hbar + b_hh)     (H,)
//   out   = sigmoid(W_y@h + b_y)                         (O,)
//   aw    = softmax(W_a@h + b_a)            (2,)
//   new_elt = sigmoid(W_n@h + b_n)          (1,)
//   new_stack = aw0*push + aw1*pop          (M,1)
//   weights = aw0 + aw1
// Output layout (fp32, flattened in return order):
//   [0 : O)            output
//   [O : O+H)          hidden (== h)
//   [O+H : O+H+M)      new_stack
//   [O+H+M]            weights

constexpr int H = 4096;
constexpr int V = 4096;
constexpr int O = 4096;
constexpr int M = 104;

constexpr int ROWS    = 4;     // output rows per block
constexpr int THREADS = 256;
constexpr int NW      = THREADS / 32;

// Scratch (no allocations allowed)
__device__ float g_hbar[H];
__device__ float g_h[H];
__device__ float g_small[3];   // [0]=W_a[0]@h, [1]=W_a[1]@h, [2]=W_n@h

__device__ __forceinline__ float warp_sum(float v) {
#pragma unroll
    for (int o = 16; o > 0; o >>= 1) v += __shfl_down_sync(0xffffffffu, v, o);
    return v;
}

// ---------------------------------------------------------------------------
// Kernel 0: hbar = W_sh * stack[0] + b_sh + hidden0     (elementwise, 16 KB x3)
// ---------------------------------------------------------------------------
__global__ void hbar_kernel(const float* __restrict__ W_sh,
                            const float* __restrict__ b_sh,
                            const float* __restrict__ hidden0,
                            const float* __restrict__ stack) {
    int i = blockIdx.x * blockDim.x + threadIdx.x;
    if (i < H) {
        g_hbar[i] = fmaf(W_sh[i], stack[0], b_sh[i] + hidden0[i]);
    }
}

// ---------------------------------------------------------------------------
// Kernel 1: h = tanh(W_ih@emb + W_hh@hbar + b_ih + b_hh)
// One block computes ROWS output rows; streams 2*ROWS matrix rows from HBM,
// vector operands (emb, hbar) come from L2 after the first wave.
// ---------------------------------------------------------------------------
__global__ void __launch_bounds__(THREADS)
h_kernel(const float* __restrict__ E, const int* __restrict__ inp,
         const float* __restrict__ W_ih, const float* __restrict__ b_ih,
         const float* __restrict__ W_hh, const float* __restrict__ b_hh,
         float* __restrict__ out) {
    __shared__ float sred[ROWS][NW];

    const float4* emb4 = (const float4*)(E + (size_t)inp[0] * V);
    const float4* hb4  = (const float4*)g_hbar;

    const int row0 = blockIdx.x * ROWS;
    float acc[ROWS];
#pragma unroll
    for (int r = 0; r < ROWS; ++r) acc[r] = 0.f;

    const float4* wi4[ROWS];
    const float4* wh4[ROWS];
#pragma unroll
    for (int r = 0; r < ROWS; ++r) {
        wi4[r] = (const float4*)(W_ih + (size_t)(row0 + r) * V);
        wh4[r] = (const float4*)(W_hh + (size_t)(row0 + r) * H);
    }

#pragma unroll
    for (int it = 0; it < (V / 4) / THREADS; ++it) {
        const int j = it * THREADS + threadIdx.x;
        const float4 e  = __ldg(emb4 + j);
        const float4 hb = __ldg(hb4 + j);
#pragma unroll
        for (int r = 0; r < ROWS; ++r) {
            const float4 a = __ldg(wi4[r] + j);
            const float4 b = __ldg(wh4[r] + j);
            acc[r] = fmaf(a.x, e.x,  acc[r]);
            acc[r] = fmaf(a.y, e.y,  acc[r]);
            acc[r] = fmaf(a.z, e.z,  acc[r]);
            acc[r] = fmaf(a.w, e.w,  acc[r]);
            acc[r] = fmaf(b.x, hb.x, acc[r]);
            acc[r] = fmaf(b.y, hb.y, acc[r]);
            acc[r] = fmaf(b.z, hb.z, acc[r]);
            acc[r] = fmaf(b.w, hb.w, acc[r]);
        }
    }

    const int lane = threadIdx.x & 31;
    const int w    = threadIdx.x >> 5;
#pragma unroll
    for (int r = 0; r < ROWS; ++r) {
        const float v = warp_sum(acc[r]);
        if (lane == 0) sred[r][w] = v;
    }
    __syncthreads();

    if (threadIdx.x < ROWS) {
        const int r = threadIdx.x;
        float t = 0.f;
#pragma unroll
        for (int k = 0; k < NW; ++k) t += sred[r][k];
        const int row = row0 + r;
        const float hv = tanhf(t + b_ih[row] + b_hh[row]);
        g_h[row]     = hv;
        out[O + row] = hv;   // hidden output region
    }
}

// ---------------------------------------------------------------------------
// Kernel 2: out = sigmoid(W_y@h + b_y); extra tail block computes the three
// small dots W_a[0]@h, W_a[1]@h, W_n@h into g_small.
// ---------------------------------------------------------------------------
__global__ void __launch_bounds__(THREADS)
y_kernel(const float* __restrict__ W_y, const float* __restrict__ b_y,
         const float* __restrict__ W_a, const float* __restrict__ W_n,
         float* __restrict__ out) {
    __shared__ float sred[ROWS][NW];
    const float4* h4 = (const float4*)g_h;
    const int lane = threadIdx.x & 31;
    const int w    = threadIdx.x >> 5;

    if (blockIdx.x < O / ROWS) {
        const int row0 = blockIdx.x * ROWS;
        float acc[ROWS];
#pragma unroll
        for (int r = 0; r < ROWS; ++r) acc[r] = 0.f;

        const float4* wy4[ROWS];
#pragma unroll
        for (int r = 0; r < ROWS; ++r)
            wy4[r] = (const float4*)(W_y + (size_t)(row0 + r) * H);

#pragma unroll
        for (int it = 0; it < (H / 4) / THREADS; ++it) {
            const int j = it * THREADS + threadIdx.x;
            const float4 hh = __ldg(h4 + j);
#pragma unroll
            for (int r = 0; r < ROWS; ++r) {
                const float4 a = __ldg(wy4[r] + j);
                acc[r] = fmaf(a.x, hh.x, acc[r]);
                acc[r] = fmaf(a.y, hh.y, acc[r]);
                acc[r] = fmaf(a.z, hh.z, acc[r]);
                acc[r] = fmaf(a.w, hh.w, acc[r]);
            }
        }

#pragma unroll
        for (int r = 0; r < ROWS; ++r) {
            const float v = warp_sum(acc[r]);
            if (lane == 0) sred[r][w] = v;
        }
        __syncthreads();

        if (threadIdx.x < ROWS) {
            const int r = threadIdx.x;
            float t = 0.f;
#pragma unroll
            for (int k = 0; k < NW; ++k) t += sred[r][k];
            const int row = row0 + r;
            out[row] = 1.f / (1.f + expf(-(t + b_y[row])));
        }
    } else {
        // tail block: three small dot products against h
        float a0 = 0.f, a1 = 0.f, an = 0.f;
        const float4* wa0 = (const float4*)W_a;
        const float4* wa1 = (const float4*)(W_a + H);
        const float4* wn  = (const float4*)W_n;
#pragma unroll
        for (int it = 0; it < (H / 4) / THREADS; ++it) {
            const int j = it * THREADS + threadIdx.x;
            const float4 hh = __ldg(h4 + j);
            const float4 x0 = __ldg(wa0 + j);
            const float4 x1 = __ldg(wa1 + j);
            const float4 x2 = __ldg(wn + j);
            a0 = fmaf(x0.x, hh.x, a0); a0 = fmaf(x0.y, hh.y, a0);
            a0 = fmaf(x0.z, hh.z, a0); a0 = fmaf(x0.w, hh.w, a0);
            a1 = fmaf(x1.x, hh.x, a1); a1 = fmaf(x1.y, hh.y, a1);
            a1 = fmaf(x1.z, hh.z, a1); a1 = fmaf(x1.w, hh.w, a1);
            an = fmaf(x2.x, hh.x, an); an = fmaf(x2.y, hh.y, an);
            an = fmaf(x2.z, hh.z, an); an = fmaf(x2.w, hh.w, an);
        }
        float v0 = warp_sum(a0);
        float v1 = warp_sum(a1);
        float v2 = warp_sum(an);
        if (lane == 0) { sred[0][w] = v0; sred[1][w] = v1; sred[2][w] = v2; }
        __syncthreads();
        if (threadIdx.x < 3) {
            const int r = threadIdx.x;
            float t = 0.f;
#pragma unroll
            for (int k = 0; k < NW; ++k) t += sred[r][k];
            g_small[r] = t;
        }
    }
}

// ---------------------------------------------------------------------------
// Kernel 3: softmax(2), new_elt, stack blend, weights.
// ---------------------------------------------------------------------------
__global__ void finalize_kernel(const float* __restrict__ stack,
                                const float* __restrict__ b_a,
                                const float* __restrict__ b_n,
                                float* __restrict__ out) {
    const float l0 = g_small[0] + b_a[0];
    const float l1 = g_small[1] + b_a[1];
    const float mx = fmaxf(l0, l1);
    const float e0 = expf(l0 - mx);
    const float e1 = expf(l1 - mx);
    const float inv = 1.f / (e0 + e1);
    const float aw0 = e0 * inv;
    const float aw1 = e1 * inv;
    const float ne  = 1.f / (1.f + expf(-(g_small[2] + b_n[0])));

    const int i = threadIdx.x;
    if (i < M) {
        const float push = (i == 0) ? ne : stack[i - 1];
        const float pop  = (i < M - 1) ? stack[i + 1] : 0.f;
        out[O + H + i] = aw0 * push + aw1 * pop;
    }
    if (i == 0) out[O + H + M] = aw0 + aw1;   // weights
}

// ---------------------------------------------------------------------------
extern "C" void kernel_launch(void* const* d_in, const int* in_sizes, int n_in,
                              void* d_out, int out_size) {
    const int*   inp     = (const int*)  d_in[0];
    const float* hidden0 = (const float*)d_in[1];
    const float* stack   = (const float*)d_in[2];
    const float* E       = (const float*)d_in[3];
    const float* W_ih    = (const float*)d_in[4];
    const float* b_ih    = (const float*)d_in[5];
    const float* W_hh    = (const float*)d_in[6];
    const float* b_hh    = (const float*)d_in[7];
    const float* W_y     = (const float*)d_in[8];
    const float* b_y     = (const float*)d_in[9];
    const float* W_n     = (const float*)d_in[10];
    const float* b_n     = (const float*)d_in[11];
    const float* W_a     = (const float*)d_in[12];
    const float* b_a     = (const float*)d_in[13];
    const float* W_sh    = (const float*)d_in[14];
    const float* b_sh    = (const float*)d_in[15];
    float* out = (float*)d_out;

    hbar_kernel<<<(H + 255) / 256, 256>>>(W_sh, b_sh, hidden0, stack);
    h_kernel<<<H / ROWS, THREADS>>>(E, inp, W_ih, b_ih, W_hh, b_hh, out);
    y_kernel<<<O / ROWS + 1, THREADS>>>(W_y, b_y, W_a, W_n, out);
    finalize_kernel<<<1, 128>>>(stack, b_a, b_n, out);
}

// round 3
// speedup vs baseline: 1.0508x; 1.0508x over previous
#include <cuda_runtime.h>

// SRNN_Softmax: one stack-RNN step, 2 plain kernels (no PDL this round).
//   hbar  = W_sh[:,0]*stack[0] + b_sh + hidden0          (H,)  [inlined]
//   h     = tanh(W_ih@emb + b_ih + W_hh@hbar + b_hh)     (H,)
//   out   = sigmoid(W_y@h + b_y)                         (O,)
//   aw    = softmax(W_a@h + b_a); new_elt = sigmoid(W_n@h + b_n)
//   new_stack = aw0*push + aw1*pop;  weights = aw0+aw1
// Output layout (fp32): [0:O) output | [O:O+H) hidden | [O+H:O+H+M) stack | [O+H+M] weights

constexpr int H = 4096;
constexpr int V = 4096;
constexpr int O = 4096;
constexpr int M = 104;

constexpr int ROWS    = 4;
constexpr int THREADS = 256;
constexpr int NW      = THREADS / 32;

__device__ float g_h[H];

__device__ __forceinline__ float warp_sum(float v) {
#pragma unroll
    for (int o = 16; o > 0; o >>= 1) v += __shfl_down_sync(0xffffffffu, v, o);
    return v;
}

// ---------------------------------------------------------------------------
// Kernel 1: h = tanh(W_ih@emb + W_hh@hbar + b_ih + b_hh), hbar inlined.
// Streams 2*ROWS matrix rows per block from HBM; vector operands are L2-hot.
// ---------------------------------------------------------------------------
__global__ void __launch_bounds__(THREADS)
h_kernel(const float* __restrict__ E, const int* __restrict__ inp,
         const float* __restrict__ W_ih, const float* __restrict__ b_ih,
         const float* __restrict__ W_hh, const float* __restrict__ b_hh,
         const float* __restrict__ W_sh, const float* __restrict__ b_sh,
         const float* __restrict__ hidden0, const float* __restrict__ stack,
         float* __restrict__ out) {
    __shared__ float sred[ROWS][NW];

    const float   s0   = stack[0];
    const float4* emb4 = (const float4*)(E + (size_t)inp[0] * V);
    const float4* ws4  = (const float4*)W_sh;
    const float4* bs4  = (const float4*)b_sh;
    const float4* h04  = (const float4*)hidden0;

    const int row0 = blockIdx.x * ROWS;
    float acc[ROWS];
#pragma unroll
    for (int r = 0; r < ROWS; ++r) acc[r] = 0.f;

    const float4* wi4[ROWS];
    const float4* wh4[ROWS];
#pragma unroll
    for (int r = 0; r < ROWS; ++r) {
        wi4[r] = (const float4*)(W_ih + (size_t)(row0 + r) * V);
        wh4[r] = (const float4*)(W_hh + (size_t)(row0 + r) * H);
    }

#pragma unroll
    for (int it = 0; it < (V / 4) / THREADS; ++it) {
        const int j = it * THREADS + threadIdx.x;
        const float4 e  = __ldg(emb4 + j);
        const float4 ws = __ldg(ws4 + j);
        const float4 bs = __ldg(bs4 + j);
        const float4 h0 = __ldg(h04 + j);
        float4 hb;
        hb.x = fmaf(ws.x, s0, bs.x + h0.x);
        hb.y = fmaf(ws.y, s0, bs.y + h0.y);
        hb.z = fmaf(ws.z, s0, bs.z + h0.z);
        hb.w = fmaf(ws.w, s0, bs.w + h0.w);
#pragma unroll
        for (int r = 0; r < ROWS; ++r) {
            const float4 a = __ldg(wi4[r] + j);
            const float4 b = __ldg(wh4[r] + j);
            acc[r] = fmaf(a.x, e.x,  acc[r]);
            acc[r] = fmaf(a.y, e.y,  acc[r]);
            acc[r] = fmaf(a.z, e.z,  acc[r]);
            acc[r] = fmaf(a.w, e.w,  acc[r]);
            acc[r] = fmaf(b.x, hb.x, acc[r]);
            acc[r] = fmaf(b.y, hb.y, acc[r]);
            acc[r] = fmaf(b.z, hb.z, acc[r]);
            acc[r] = fmaf(b.w, hb.w, acc[r]);
        }
    }

    const int lane = threadIdx.x & 31;
    const int w    = threadIdx.x >> 5;
#pragma unroll
    for (int r = 0; r < ROWS; ++r) {
        const float v = warp_sum(acc[r]);
        if (lane == 0) sred[r][w] = v;
    }
    __syncthreads();

    if (threadIdx.x < ROWS) {
        const int r = threadIdx.x;
        float t = 0.f;
#pragma unroll
        for (int k = 0; k < NW; ++k) t += sred[r][k];
        const int row = row0 + r;
        const float hv = tanhf(t + b_ih[row] + b_hh[row]);
        g_h[row]     = hv;
        out[O + row] = hv;
    }
}

// ---------------------------------------------------------------------------
// Kernel 2: out = sigmoid(W_y@h + b_y); tail block computes the three small
// dots AND finishes softmax/sigmoid/stack-blend (no separate finalize kernel).
// ---------------------------------------------------------------------------
__global__ void __launch_bounds__(THREADS)
y_kernel(const float* __restrict__ W_y, const float* __restrict__ b_y,
         const float* __restrict__ W_a, const float* __restrict__ b_a,
         const float* __restrict__ W_n, const float* __restrict__ b_n,
         const float* __restrict__ stack,
         float* __restrict__ out) {
    __shared__ float sred[ROWS][NW];
    __shared__ float ssmall[3];
    const int lane = threadIdx.x & 31;
    const int w    = threadIdx.x >> 5;
    const float4* h4 = (const float4*)g_h;

    if (blockIdx.x < O / ROWS) {
        const int row0 = blockIdx.x * ROWS;
        float acc[ROWS];
#pragma unroll
        for (int r = 0; r < ROWS; ++r) acc[r] = 0.f;

        const float4* wy4[ROWS];
#pragma unroll
        for (int r = 0; r < ROWS; ++r)
            wy4[r] = (const float4*)(W_y + (size_t)(row0 + r) * H);

#pragma unroll
        for (int it = 0; it < (H / 4) / THREADS; ++it) {
            const int j = it * THREADS + threadIdx.x;
            const float4 hh = __ldg(h4 + j);
#pragma unroll
            for (int r = 0; r < ROWS; ++r) {
                const float4 a = __ldg(wy4[r] + j);
                acc[r] = fmaf(a.x, hh.x, acc[r]);
                acc[r] = fmaf(a.y, hh.y, acc[r]);
                acc[r] = fmaf(a.z, hh.z, acc[r]);
                acc[r] = fmaf(a.w, hh.w, acc[r]);
            }
        }

#pragma unroll
        for (int r = 0; r < ROWS; ++r) {
            const float v = warp_sum(acc[r]);
            if (lane == 0) sred[r][w] = v;
        }
        __syncthreads();

        if (threadIdx.x < ROWS) {
            const int r = threadIdx.x;
            float t = 0.f;
#pragma unroll
            for (int k = 0; k < NW; ++k) t += sred[r][k];
            const int row = row0 + r;
            out[row] = 1.f / (1.f + expf(-(t + b_y[row])));
        }
    } else {
        // Tail block: W_a (2 rows) + W_n (1 row) dots, then finalize.
        const float4* wa0 = (const float4*)W_a;
        const float4* wa1 = (const float4*)(W_a + H);
        const float4* wn  = (const float4*)W_n;
        float a0 = 0.f, a1 = 0.f, an = 0.f;
#pragma unroll
        for (int it = 0; it < (H / 4) / THREADS; ++it) {
            const int j = it * THREADS + threadIdx.x;
            const float4 hh = __ldg(h4 + j);
            const float4 x0 = __ldg(wa0 + j);
            const float4 x1 = __ldg(wa1 + j);
            const float4 x2 = __ldg(wn + j);
            a0 = fmaf(x0.x, hh.x, a0); a0 = fmaf(x0.y, hh.y, a0);
            a0 = fmaf(x0.z, hh.z, a0); a0 = fmaf(x0.w, hh.w, a0);
            a1 = fmaf(x1.x, hh.x, a1); a1 = fmaf(x1.y, hh.y, a1);
            a1 = fmaf(x1.z, hh.z, a1); a1 = fmaf(x1.w, hh.w, a1);
            an = fmaf(x2.x, hh.x, an); an = fmaf(x2.y, hh.y, an);
            an = fmaf(x2.z, hh.z, an); an = fmaf(x2.w, hh.w, an);
        }
        const float v0 = warp_sum(a0);
        const float v1 = warp_sum(a1);
        const float v2 = warp_sum(an);
        if (lane == 0) { sred[0][w] = v0; sred[1][w] = v1; sred[2][w] = v2; }
        __syncthreads();
        if (threadIdx.x < 3) {
            const int r = threadIdx.x;
            float t = 0.f;
#pragma unroll
            for (int k = 0; k < NW; ++k) t += sred[r][k];
            ssmall[r] = t;
        }
        __syncthreads();

        const float l0 = ssmall[0] + b_a[0];
        const float l1 = ssmall[1] + b_a[1];
        const float mx = fmaxf(l0, l1);
        const float e0 = expf(l0 - mx);
        const float e1 = expf(l1 - mx);
        const float inv = 1.f / (e0 + e1);
        const float aw0 = e0 * inv;
        const float aw1 = e1 * inv;
        const float ne  = 1.f / (1.f + expf(-(ssmall[2] + b_n[0])));

        const int i = threadIdx.x;
        if (i < M) {
            const float push = (i == 0) ? ne : stack[i - 1];
            const float pop  = (i < M - 1) ? stack[i + 1] : 0.f;
            out[O + H + i] = aw0 * push + aw1 * pop;
        }
        if (i == 0) out[O + H + M] = aw0 + aw1;
    }
}

// ---------------------------------------------------------------------------
extern "C" void kernel_launch(void* const* d_in, const int* in_sizes, int n_in,
                              void* d_out, int out_size) {
    const int*   inp     = (const int*)  d_in[0];
    const float* hidden0 = (const float*)d_in[1];
    const float* stack   = (const float*)d_in[2];
    const float* E       = (const float*)d_in[3];
    const float* W_ih    = (const float*)d_in[4];
    const float* b_ih    = (const float*)d_in[5];
    const float* W_hh    = (const float*)d_in[6];
    const float* b_hh    = (const float*)d_in[7];
    const float* W_y     = (const float*)d_in[8];
    const float* b_y     = (const float*)d_in[9];
    const float* W_n     = (const float*)d_in[10];
    const float* b_n     = (const float*)d_in[11];
    const float* W_a     = (const float*)d_in[12];
    const float* b_a     = (const float*)d_in[13];
    const float* W_sh    = (const float*)d_in[14];
    const float* b_sh    = (const float*)d_in[15];
    float* out = (float*)d_out;

    h_kernel<<<H / ROWS, THREADS>>>(E, inp, W_ih, b_ih, W_hh, b_hh,
                                    W_sh, b_sh, hidden0, stack, out);
    y_kernel<<<O / ROWS + 1, THREADS>>>(W_y, b_y, W_a, b_a, W_n, b_n, stack, out);
}

// round 5
// speedup vs baseline: 1.0971x; 1.0440x over previous
#include <cuda_runtime.h>

// SRNN_Softmax: one stack-RNN step, 2 plain kernels.
//   hbar  = W_sh[:,0]*stack[0] + b_sh + hidden0          (H,)  [inlined]
//   h     = tanh(W_ih@emb + b_ih + W_hh@hbar + b_hh)     (H,)
//   out   = sigmoid(W_y@h + b_y)                         (O,)
//   aw    = softmax(W_a@h + b_a); new_elt = sigmoid(W_n@h + b_n)
//   new_stack = aw0*push + aw1*pop;  weights = aw0+aw1
// Output layout (fp32): [0:O) output | [O:O+H) hidden | [O+H:O+H+M) stack | [O+H+M] weights

constexpr int H = 4096;
constexpr int V = 4096;
constexpr int O = 4096;
constexpr int M = 104;

constexpr int ROWS_H  = 4;     // rows/block, h GEMV (8 matrix streams)
constexpr int ROWS_Y  = 8;     // rows/block, y GEMV (8 matrix streams)
constexpr int THREADS = 256;
constexpr int NW      = THREADS / 32;

__device__ float g_h[H];

__device__ __forceinline__ float warp_sum(float v) {
#pragma unroll
    for (int o = 16; o > 0; o >>= 1) v += __shfl_down_sync(0xffffffffu, v, o);
    return v;
}

// ---------------------------------------------------------------------------
// Kernel 1: h = tanh(W_ih@emb + W_hh@hbar + b_ih + b_hh), hbar inlined.
// Matrix rows are single-use -> streaming loads (__ldcs); vectors stay L2-hot.
// ---------------------------------------------------------------------------
__global__ void __launch_bounds__(THREADS)
h_kernel(const float* __restrict__ E, const int* __restrict__ inp,
         const float* __restrict__ W_ih, const float* __restrict__ b_ih,
         const float* __restrict__ W_hh, const float* __restrict__ b_hh,
         const float* __restrict__ W_sh, const float* __restrict__ b_sh,
         const float* __restrict__ hidden0, const float* __restrict__ stack,
         float* __restrict__ out) {
    __shared__ float sred[ROWS_H][NW];

    const float   s0   = stack[0];
    const float4* emb4 = (const float4*)(E + (size_t)inp[0] * V);
    const float4* ws4  = (const float4*)W_sh;
    const float4* bs4  = (const float4*)b_sh;
    const float4* h04  = (const float4*)hidden0;

    const int row0 = blockIdx.x * ROWS_H;
    float acc[ROWS_H];
#pragma unroll
    for (int r = 0; r < ROWS_H; ++r) acc[r] = 0.f;

    const float4* wi4[ROWS_H];
    const float4* wh4[ROWS_H];
#pragma unroll
    for (int r = 0; r < ROWS_H; ++r) {
        wi4[r] = (const float4*)(W_ih + (size_t)(row0 + r) * V);
        wh4[r] = (const float4*)(W_hh + (size_t)(row0 + r) * H);
    }

#pragma unroll
    for (int it = 0; it < (V / 4) / THREADS; ++it) {
        const int j = it * THREADS + threadIdx.x;
        const float4 e  = __ldg(emb4 + j);
        const float4 ws = __ldg(ws4 + j);
        const float4 bs = __ldg(bs4 + j);
        const float4 h0 = __ldg(h04 + j);
        float4 hb;
        hb.x = fmaf(ws.x, s0, bs.x + h0.x);
        hb.y = fmaf(ws.y, s0, bs.y + h0.y);
        hb.z = fmaf(ws.z, s0, bs.z + h0.z);
        hb.w = fmaf(ws.w, s0, bs.w + h0.w);
#pragma unroll
        for (int r = 0; r < ROWS_H; ++r) {
            const float4 a = __ldcs(wi4[r] + j);
            const float4 b = __ldcs(wh4[r] + j);
            acc[r] = fmaf(a.x, e.x,  acc[r]);
            acc[r] = fmaf(a.y, e.y,  acc[r]);
            acc[r] = fmaf(a.z, e.z,  acc[r]);
            acc[r] = fmaf(a.w, e.w,  acc[r]);
            acc[r] = fmaf(b.x, hb.x, acc[r]);
            acc[r] = fmaf(b.y, hb.y, acc[r]);
            acc[r] = fmaf(b.z, hb.z, acc[r]);
            acc[r] = fmaf(b.w, hb.w, acc[r]);
        }
    }

    const int lane = threadIdx.x & 31;
    const int w    = threadIdx.x >> 5;
#pragma unroll
    for (int r = 0; r < ROWS_H; ++r) {
        const float v = warp_sum(acc[r]);
        if (lane == 0) sred[r][w] = v;
    }
    __syncthreads();

    if (threadIdx.x < ROWS_H) {
        const int r = threadIdx.x;
        float t = 0.f;
#pragma unroll
        for (int k = 0; k < NW; ++k) t += sred[r][k];
        const int row = row0 + r;
        const float hv = tanhf(t + b_ih[row] + b_hh[row]);
        g_h[row]     = hv;
        out[O + row] = hv;
    }
}

// ---------------------------------------------------------------------------
// Kernel 2: out = sigmoid(W_y@h + b_y) with 8 rows/block; tail block computes
// the three small dots AND finishes softmax/sigmoid/stack-blend.
// ---------------------------------------------------------------------------
__global__ void __launch_bounds__(THREADS)
y_kernel(const float* __restrict__ W_y, const float* __restrict__ b_y,
         const float* __restrict__ W_a, const float* __restrict__ b_a,
         const float* __restrict__ W_n, const float* __restrict__ b_n,
         const float* __restrict__ stack,
         float* __restrict__ out) {
    __shared__ float sred[ROWS_Y][NW];
    __shared__ float ssmall[3];
    const int lane = threadIdx.x & 31;
    const int w    = threadIdx.x >> 5;
    const float4* h4 = (const float4*)g_h;

    if (blockIdx.x < O / ROWS_Y) {
        const int row0 = blockIdx.x * ROWS_Y;
        float acc[ROWS_Y];
#pragma unroll
        for (int r = 0; r < ROWS_Y; ++r) acc[r] = 0.f;

        const float4* wy4[ROWS_Y];
#pragma unroll
        for (int r = 0; r < ROWS_Y; ++r)
            wy4[r] = (const float4*)(W_y + (size_t)(row0 + r) * H);

#pragma unroll
        for (int it = 0; it < (H / 4) / THREADS; ++it) {
            const int j = it * THREADS + threadIdx.x;
            const float4 hh = __ldg(h4 + j);
#pragma unroll
            for (int r = 0; r < ROWS_Y; ++r) {
                const float4 a = __ldcs(wy4[r] + j);
                acc[r] = fmaf(a.x, hh.x, acc[r]);
                acc[r] = fmaf(a.y, hh.y, acc[r]);
                acc[r] = fmaf(a.z, hh.z, acc[r]);
                acc[r] = fmaf(a.w, hh.w, acc[r]);
            }
        }

#pragma unroll
        for (int r = 0; r < ROWS_Y; ++r) {
            const float v = warp_sum(acc[r]);
            if (lane == 0) sred[r][w] = v;
        }
        __syncthreads();

        if (threadIdx.x < ROWS_Y) {
            const int r = threadIdx.x;
            float t = 0.f;
#pragma unroll
            for (int k = 0; k < NW; ++k) t += sred[r][k];
            const int row = row0 + r;
            out[row] = 1.f / (1.f + expf(-(t + b_y[row])));
        }
    } else {
        // Tail block: W_a (2 rows) + W_n (1 row) dots, then finalize.
        const float4* wa0 = (const float4*)W_a;
        const float4* wa1 = (const float4*)(W_a + H);
        const float4* wn  = (const float4*)W_n;
        float a0 = 0.f, a1 = 0.f, an = 0.f;
#pragma unroll
        for (int it = 0; it < (H / 4) / THREADS; ++it) {
            const int j = it * THREADS + threadIdx.x;
            const float4 hh = __ldg(h4 + j);
            const float4 x0 = __ldg(wa0 + j);
            const float4 x1 = __ldg(wa1 + j);
            const float4 x2 = __ldg(wn + j);
            a0 = fmaf(x0.x, hh.x, a0); a0 = fmaf(x0.y, hh.y, a0);
            a0 = fmaf(x0.z, hh.z, a0); a0 = fmaf(x0.w, hh.w, a0);
            a1 = fmaf(x1.x, hh.x, a1); a1 = fmaf(x1.y, hh.y, a1);
            a1 = fmaf(x1.z, hh.z, a1); a1 = fmaf(x1.w, hh.w, a1);
            an = fmaf(x2.x, hh.x, an); an = fmaf(x2.y, hh.y, an);
            an = fmaf(x2.z, hh.z, an); an = fmaf(x2.w, hh.w, an);
        }
        const float v0 = warp_sum(a0);
        const float v1 = warp_sum(a1);
        const float v2 = warp_sum(an);
        if (lane == 0) { sred[0][w] = v0; sred[1][w] = v1; sred[2][w] = v2; }
        __syncthreads();
        if (threadIdx.x < 3) {
            const int r = threadIdx.x;
            float t = 0.f;
#pragma unroll
            for (int k = 0; k < NW; ++k) t += sred[r][k];
            ssmall[r] = t;
        }
        __syncthreads();

        const float l0 = ssmall[0] + b_a[0];
        const float l1 = ssmall[1] + b_a[1];
        const float mx = fmaxf(l0, l1);
        const float e0 = expf(l0 - mx);
        const float e1 = expf(l1 - mx);
        const float inv = 1.f / (e0 + e1);
        const float aw0 = e0 * inv;
        const float aw1 = e1 * inv;
        const float ne  = 1.f / (1.f + expf(-(ssmall[2] + b_n[0])));

        const int i = threadIdx.x;
        if (i < M) {
            const float push = (i == 0) ? ne : stack[i - 1];
            const float pop  = (i < M - 1) ? stack[i + 1] : 0.f;
            out[O + H + i] = aw0 * push + aw1 * pop;
        }
        if (i == 0) out[O + H + M] = aw0 + aw1;
    }
}

// ---------------------------------------------------------------------------
extern "C" void kernel_launch(void* const* d_in, const int* in_sizes, int n_in,
                              void* d_out, int out_size) {
    const int*   inp     = (const int*)  d_in[0];
    const float* hidden0 = (const float*)d_in[1];
    const float* stack   = (const float*)d_in[2];
    const float* E       = (const float*)d_in[3];
    const float* W_ih    = (const float*)d_in[4];
    const float* b_ih    = (const float*)d_in[5];
    const float* W_hh    = (const float*)d_in[6];
    const float* b_hh    = (const float*)d_in[7];
    const float* W_y     = (const float*)d_in[8];
    const float* b_y     = (const float*)d_in[9];
    const float* W_n     = (const float*)d_in[10];
    const float* b_n     = (const float*)d_in[11];
    const float* W_a     = (const float*)d_in[12];
    const float* b_a     = (const float*)d_in[13];
    const float* W_sh    = (const float*)d_in[14];
    const float* b_sh    = (const float*)d_in[15];
    float* out = (float*)d_out;

    h_kernel<<<H / ROWS_H, THREADS>>>(E, inp, W_ih, b_ih, W_hh, b_hh,
                                      W_sh, b_sh, hidden0, stack, out);
    y_kernel<<<O / ROWS_Y + 1, THREADS>>>(W_y, b_y, W_a, b_a, W_n, b_n, stack, out);
}